// round 14
// baseline (speedup 1.0000x reference)
#include <cuda_runtime.h>

typedef unsigned long long u64;
typedef unsigned int u32;

// ---------------- packed helpers (sm_10x) ----------------
__device__ __forceinline__ u64 ffma2(u64 a, u64 b, u64 c) {
    u64 d;
    asm("fma.rn.f32x2 %0, %1, %2, %3;" : "=l"(d) : "l"(a), "l"(b), "l"(c));
    return d;
}
__device__ __forceinline__ u64 mul2(u64 a, u64 b) {
    u64 d;
    asm("mul.rn.f32x2 %0, %1, %2;" : "=l"(d) : "l"(a), "l"(b));
    return d;
}
__device__ __forceinline__ u64 pack2(float lo, float hi) {
    u64 r;
    asm("mov.b64 %0, {%1, %2};" : "=l"(r) : "f"(lo), "f"(hi));
    return r;
}
__device__ __forceinline__ void unpack2(u64 v, float& lo, float& hi) {
    asm("mov.b64 {%0, %1}, %2;" : "=f"(lo), "=f"(hi) : "l"(v));
}
__device__ __forceinline__ float ex2_ap(float x) {
    float y;
    asm("ex2.approx.f32 %0, %1;" : "=f"(y) : "f"(x));
    return y;
}
__device__ __forceinline__ float lg2_ap(float x) {
    float y;
    asm("lg2.approx.f32 %0, %1;" : "=f"(y) : "f"(x));
    return y;
}
// ---- fp16x2 core ----
__device__ __forceinline__ u32 hfma2(u32 a, u32 b, u32 c) {
    u32 d;
    asm("fma.rn.f16x2 %0, %1, %2, %3;" : "=r"(d) : "r"(a), "r"(b), "r"(c));
    return d;
}
__device__ __forceinline__ u32 tanh_h2(u32 v) {
    u32 d;
    asm("tanh.approx.f16x2 %0, %1;" : "=r"(d) : "r"(v));
    return d;
}
__device__ __forceinline__ u32 pack_h2(float lo, float hi) {
    u32 d;
    asm("cvt.rn.f16x2.f32 %0, %1, %2;" : "=r"(d) : "f"(hi), "f"(lo));
    return d;
}
__device__ __forceinline__ u64 h2_to_f32x2(u32 v) {
    u64 d;
    asm("{\n\t.reg .b16 l, h;\n\t.reg .f32 flo, fhi;\n\tmov.b32 {l, h}, %1;\n\t"
        "cvt.f32.f16 flo, l;\n\tcvt.f32.f16 fhi, h;\n\tmov.b64 %0, {flo, fhi};\n\t}"
        : "=l"(d) : "r"(v));
    return d;
}

// ---------------- constant tables ----------------
enum {
    O_W1 = 0,   O_B1 = 128,
    O_W2 = 144, O_B2 = 400,
    O_W3 = 416, O_B3 = 608,
    O_W4 = 620, O_B4 = 716,
    O_W5 = 724, O_B5 = 756,
    O_WH = 760, O_BH = 776,
    W_TOTAL = 780
};
enum { D_TOTAL = 21 };  // D[0..17]=Wf dup, D[18]=bf0, D[19]=bf1, D[20]=-gamma*log2e

struct CParams {
    u32 H[W_TOTAL];
    u64 D[D_TOTAL];
    u32 pad;
};

__constant__ CParams cP;
__device__ CParams gScratch;

#define LOG2E 1.4426950408889634f
#define LN2   0.6931471805599453f

// ---------------- prep kernel ----------------
__global__ void prep_kernel(
    const float* __restrict__ W1, const float* __restrict__ b1,
    const float* __restrict__ W2, const float* __restrict__ b2,
    const float* __restrict__ W3, const float* __restrict__ b3,
    const float* __restrict__ W4, const float* __restrict__ b4,
    const float* __restrict__ W5, const float* __restrict__ b5,
    const float* __restrict__ Wh, const float* __restrict__ bh,
    const float* __restrict__ Wf, const float* __restrict__ bf,
    const float* __restrict__ gamma)
{
    int tid = threadIdx.x;
#define CP_(off, src, n)                                            \
    for (int i = tid; i < (n); i += blockDim.x) {                   \
        float f = (src)[i];                                         \
        u32 h;                                                      \
        asm("cvt.rn.f16x2.f32 %0, %1, %1;" : "=r"(h) : "f"(f));     \
        gScratch.H[(off) + i] = h;                                  \
    }
    CP_(O_W1, W1, 128); CP_(O_B1, b1, 16);
    CP_(O_W2, W2, 256); CP_(O_B2, b2, 16);
    CP_(O_W3, W3, 192); CP_(O_B3, b3, 12);
    CP_(O_W4, W4, 96);  CP_(O_B4, b4, 8);
    CP_(O_W5, W5, 32);  CP_(O_B5, b5, 4);
    CP_(O_WH, Wh, 16);  CP_(O_BH, bh, 4);
#undef CP_
    if (tid < 18) { float f = Wf[tid]; gScratch.D[tid] = pack2(f, f); }
    if (tid == 18) { float f = bf[0]; gScratch.D[18] = pack2(f, f); }
    if (tid == 19) { float f = bf[1]; gScratch.D[19] = pack2(f, f); }
    if (tid == 20) { float f = -gamma[0] * LOG2E; gScratch.D[20] = pack2(f, f); }
}

// ---------------- fp16x2 dense layer on THREE packed pairs (6 samples) ----------------
// Each weight LDCU feeds three HFMA2s (3 independent chains per j).
template <int OFF_W, int OFF_B, int IN, int OUT, bool ACT>
__device__ __forceinline__ void layer_h3(
    const u32* __restrict__ in0, const u32* __restrict__ in1, const u32* __restrict__ in2,
    u32* __restrict__ out0, u32* __restrict__ out1, u32* __restrict__ out2)
{
#pragma unroll
    for (int j = 0; j < OUT; j++) {
        u32 a0 = cP.H[OFF_B + j];
        u32 a1 = a0, a2 = a0;
#pragma unroll
        for (int i = 0; i < IN; i++) {
            u32 w = cP.H[OFF_W + j * IN + i];
            a0 = hfma2(in0[i], w, a0);
            a1 = hfma2(in1[i], w, a1);
            a2 = hfma2(in2[i], w, a2);
        }
        if (ACT) { a0 = tanh_h2(a0); a1 = tanh_h2(a1); a2 = tanh_h2(a2); }
        out0[j] = a0;
        out1[j] = a1;
        out2[j] = a2;
    }
}
// Two-pair variant (for the K=4 remainder kernel).
template <int OFF_W, int OFF_B, int IN, int OUT, bool ACT>
__device__ __forceinline__ void layer_h2(
    const u32* __restrict__ in0, const u32* __restrict__ in1,
    u32* __restrict__ out0, u32* __restrict__ out1)
{
#pragma unroll
    for (int j = 0; j < OUT; j++) {
        u32 a0 = cP.H[OFF_B + j];
        u32 a1 = a0;
#pragma unroll
        for (int i = 0; i < IN; i++) {
            u32 w = cP.H[OFF_W + j * IN + i];
            a0 = hfma2(in0[i], w, a0);
            a1 = hfma2(in1[i], w, a1);
        }
        if (ACT) { a0 = tanh_h2(a0); a1 = tanh_h2(a1); }
        out0[j] = a0;
        out1[j] = a1;
    }
}

// ---- f32 tail ----
__device__ __forceinline__ void tail_pair(const u64* __restrict__ A, u64& o0, u64& o1) {
    u64 s2 = mul2(A[0], A[0]);
    s2 = ffma2(A[1], A[1], s2);
    s2 = ffma2(A[2], A[2], s2);
    s2 = ffma2(A[3], A[3], s2);
    u64 g = mul2(s2, cP.D[20]);
    float glo, ghi;
    unpack2(g, glo, ghi);
    u64 k = pack2(ex2_ap(glo), ex2_ap(ghi));
    o0 = cP.D[18];
    o0 = ffma2(A[0], cP.D[0], o0);
    o0 = ffma2(A[1], cP.D[1], o0);
    o0 = ffma2(A[2], cP.D[2], o0);
    o0 = ffma2(A[3], cP.D[3], o0);
    o0 = ffma2(k,    cP.D[8], o0);
    o1 = cP.D[19];
    o1 = ffma2(A[0], cP.D[9],  o1);
    o1 = ffma2(A[1], cP.D[10], o1);
    o1 = ffma2(A[2], cP.D[11], o1);
    o1 = ffma2(A[3], cP.D[12], o1);
    o1 = ffma2(k,    cP.D[17], o1);
}

__device__ __forceinline__ void lsm2(float a, float b, float& ra, float& rb) {
    float m  = fmaxf(a, b);
    float mn = fminf(a, b);
    float lse = m + lg2_ap(1.0f + ex2_ap((mn - m) * LOG2E)) * LN2;
    ra = a - lse; rb = b - lse;
}

// Tail+store for one h2 pair-group (cls in Hc[0..3]) at sample index pbase.
__device__ __forceinline__ void finish_pair(const u32* __restrict__ Hc,
                                            float* __restrict__ out, int pbase) {
    u64 A[4];
#pragma unroll
    for (int j = 0; j < 4; j++) A[j] = h2_to_f32x2(Hc[j]);
    u64 o0, o1;
    tail_pair(A, o0, o1);
    float la0, lb0, la1, lb1;
    unpack2(o0, la0, lb0);
    unpack2(o1, la1, lb1);
    float r0a, r0b, r1a, r1b;
    lsm2(la0, la1, r0a, r0b);
    lsm2(lb0, lb1, r1a, r1b);
    *(float4*)(out + (size_t)pbase * 2) = make_float4(r0a, r0b, r1a, r1b);
}

__device__ __forceinline__ void load_pair_h2(const float* __restrict__ x,
                                             int s0, int s1, u32* __restrict__ H) {
    const float4* p0 = (const float4*)(x + (size_t)s0 * 8);
    const float4* p1 = (const float4*)(x + (size_t)s1 * 8);
    float4 a = p0[0], b = p0[1];
    float4 c = p1[0], d = p1[1];
    H[0] = pack_h2(a.x, c.x); H[1] = pack_h2(a.y, c.y);
    H[2] = pack_h2(a.z, c.z); H[3] = pack_h2(a.w, c.w);
    H[4] = pack_h2(b.x, d.x); H[5] = pack_h2(b.y, d.y);
    H[6] = pack_h2(b.z, d.z); H[7] = pack_h2(b.w, d.w);
}

// ---------------- K=6 exact kernel (block covers 768 samples) ----------------
__global__ __launch_bounds__(128, 3) void qcnn6(
    const float* __restrict__ x, float* __restrict__ out)
{
    int base = blockIdx.x * 768 + threadIdx.x * 6;

    u32 H0[16], H1[16], H2[16], G0[16], G1[16], G2[16];
    load_pair_h2(x, base,     base + 1, H0);
    load_pair_h2(x, base + 2, base + 3, H1);
    load_pair_h2(x, base + 4, base + 5, H2);

    layer_h3<O_W1, O_B1, 8,  16, true >(H0, H1, H2, G0, G1, G2);
    layer_h3<O_W2, O_B2, 16, 16, true >(G0, G1, G2, H0, H1, H2);
    layer_h3<O_W3, O_B3, 16, 12, true >(H0, H1, H2, G0, G1, G2);
    layer_h3<O_W4, O_B4, 12, 8,  true >(G0, G1, G2, H0, H1, H2);
    layer_h3<O_W5, O_B5, 8,  4,  true >(H0, H1, H2, G0, G1, G2);
    layer_h3<O_WH, O_BH, 4,  4,  false>(G0, G1, G2, H0, H1, H2);  // cls in H*[0..3]

    finish_pair(H0, out, base);
    finish_pair(H1, out, base + 2);
    finish_pair(H2, out, base + 4);
}

// ---------------- K=4 kernel with offset (remainder / generic) ----------------
template <bool EXACT>
__global__ __launch_bounds__(128, 4) void qcnn4(
    const float* __restrict__ x, float* __restrict__ out, int start, int nb)
{
    int t = blockIdx.x * blockDim.x + threadIdx.x;
    int base = start + t * 4;
    if (!EXACT && base >= nb) return;

    u32 H0[16], H1[16], G0[16], G1[16];
    if (EXACT || base + 4 <= nb) {
        load_pair_h2(x, base,     base + 1, H0);
        load_pair_h2(x, base + 2, base + 3, H1);
    } else {
        int s1 = (base + 1 < nb) ? base + 1 : nb - 1;
        int s2 = (base + 2 < nb) ? base + 2 : nb - 1;
        int s3 = (base + 3 < nb) ? base + 3 : nb - 1;
        load_pair_h2(x, base, s1, H0);
        load_pair_h2(x, s2, s3, H1);
    }

    layer_h2<O_W1, O_B1, 8,  16, true >(H0, H1, G0, G1);
    layer_h2<O_W2, O_B2, 16, 16, true >(G0, G1, H0, H1);
    layer_h2<O_W3, O_B3, 16, 12, true >(H0, H1, G0, G1);
    layer_h2<O_W4, O_B4, 12, 8,  true >(G0, G1, H0, H1);
    layer_h2<O_W5, O_B5, 8,  4,  true >(H0, H1, G0, G1);
    layer_h2<O_WH, O_BH, 4,  4,  false>(G0, G1, H0, H1);

    if (EXACT || base + 4 <= nb) {
        finish_pair(H0, out, base);
        finish_pair(H1, out, base + 2);
    } else {
        // slow tail path: compute per sample, guarded scalar stores
        u64 A0[4], A1[4];
#pragma unroll
        for (int j = 0; j < 4; j++) { A0[j] = h2_to_f32x2(H0[j]); A1[j] = h2_to_f32x2(H1[j]); }
        u64 q0, q1, q2, q3;
        tail_pair(A0, q0, q1);
        tail_pair(A1, q2, q3);
        float v0a, v0b, v1a, v1b, v2a, v2b, v3a, v3b;
        unpack2(q0, v0a, v1a);
        unpack2(q1, v0b, v1b);
        unpack2(q2, v2a, v3a);
        unpack2(q3, v2b, v3b);
        float rs[4][2];
        lsm2(v0a, v0b, rs[0][0], rs[0][1]);
        lsm2(v1a, v1b, rs[1][0], rs[1][1]);
        lsm2(v2a, v2b, rs[2][0], rs[2][1]);
        lsm2(v3a, v3b, rs[3][0], rs[3][1]);
#pragma unroll
        for (int s = 0; s < 4; s++) {
            if (base + s < nb) {
                out[(base + s) * 2 + 0] = rs[s][0];
                out[(base + s) * 2 + 1] = rs[s][1];
            }
        }
    }
}

extern "C" void kernel_launch(void* const* d_in, const int* in_sizes, int n_in,
                              void* d_out, int out_size) {
    const float* x  = (const float*)d_in[0];
    const float* W1 = (const float*)d_in[1];
    const float* b1 = (const float*)d_in[2];
    const float* W2 = (const float*)d_in[3];
    const float* b2 = (const float*)d_in[4];
    const float* W3 = (const float*)d_in[5];
    const float* b3 = (const float*)d_in[6];
    const float* W4 = (const float*)d_in[7];
    const float* b4 = (const float*)d_in[8];
    const float* W5 = (const float*)d_in[9];
    const float* b5 = (const float*)d_in[10];
    const float* Wh = (const float*)d_in[11];
    const float* bh = (const float*)d_in[12];
    const float* Wf = (const float*)d_in[13];
    const float* bf = (const float*)d_in[14];
    const float* gm = (const float*)d_in[15];

    // 1) build fp16x2 weight table in device scratch
    prep_kernel<<<1, 256>>>(W1, b1, W2, b2, W3, b3, W4, b4, W5, b5,
                            Wh, bh, Wf, bf, gm);

    // 2) move into the constant bank (D2D async copy — graph-capturable)
    void* scratch_addr = nullptr;
    cudaGetSymbolAddress(&scratch_addr, gScratch);
    cudaMemcpyToSymbolAsync(cP, scratch_addr, sizeof(CParams), 0,
                            cudaMemcpyDeviceToDevice, 0);

    // 3) main: K=6 exact blocks + K=4 remainder
    int nb = in_sizes[0] / 8;
    int blocks6 = nb / 768;                  // each covers 768 samples exactly
    int start4 = blocks6 * 768;
    int rem = nb - start4;
    if (blocks6 > 0) {
        qcnn6<<<blocks6, 128>>>(x, (float*)d_out);
    }
    if (rem > 0) {
        int threads = 128;
        int spb = threads * 4;
        int blocks4 = (rem + spb - 1) / spb;
        if (rem % 4 == 0 && (rem / 4) % threads == 0) {
            qcnn4<true><<<blocks4, threads>>>(x, (float*)d_out, start4, nb);
        } else {
            qcnn4<false><<<blocks4, threads>>>(x, (float*)d_out, start4, nb);
        }
    }
}

// round 15
// speedup vs baseline: 1.1474x; 1.1474x over previous
#include <cuda_runtime.h>

typedef unsigned long long u64;
typedef unsigned int u32;

// ---------------- packed helpers (sm_10x) ----------------
__device__ __forceinline__ u64 ffma2(u64 a, u64 b, u64 c) {
    u64 d;
    asm("fma.rn.f32x2 %0, %1, %2, %3;" : "=l"(d) : "l"(a), "l"(b), "l"(c));
    return d;
}
__device__ __forceinline__ u64 mul2(u64 a, u64 b) {
    u64 d;
    asm("mul.rn.f32x2 %0, %1, %2;" : "=l"(d) : "l"(a), "l"(b));
    return d;
}
__device__ __forceinline__ u64 pack2(float lo, float hi) {
    u64 r;
    asm("mov.b64 %0, {%1, %2};" : "=l"(r) : "f"(lo), "f"(hi));
    return r;
}
__device__ __forceinline__ void unpack2(u64 v, float& lo, float& hi) {
    asm("mov.b64 {%0, %1}, %2;" : "=f"(lo), "=f"(hi) : "l"(v));
}
__device__ __forceinline__ float ex2_ap(float x) {
    float y;
    asm("ex2.approx.f32 %0, %1;" : "=f"(y) : "f"(x));
    return y;
}
__device__ __forceinline__ float lg2_ap(float x) {
    float y;
    asm("lg2.approx.f32 %0, %1;" : "=f"(y) : "f"(x));
    return y;
}
// ---- fp16x2 core (HFMA2: 32-bit regs -> rt2; won 61.2us in R12) ----
__device__ __forceinline__ u32 hfma2(u32 a, u32 b, u32 c) {
    u32 d;
    asm("fma.rn.f16x2 %0, %1, %2, %3;" : "=r"(d) : "r"(a), "r"(b), "r"(c));
    return d;
}
__device__ __forceinline__ u32 tanh_h2(u32 v) {
    u32 d;
    asm("tanh.approx.f16x2 %0, %1;" : "=r"(d) : "r"(v));
    return d;
}
__device__ __forceinline__ u32 pack_h2(float lo, float hi) {
    u32 d;
    asm("cvt.rn.f16x2.f32 %0, %1, %2;" : "=r"(d) : "f"(hi), "f"(lo));
    return d;
}
__device__ __forceinline__ u64 h2_to_f32x2(u32 v) {
    u64 d;
    asm("{\n\t.reg .b16 l, h;\n\t.reg .f32 flo, fhi;\n\tmov.b32 {l, h}, %1;\n\t"
        "cvt.f32.f16 flo, l;\n\tcvt.f32.f16 fhi, h;\n\tmov.b64 %0, {flo, fhi};\n\t}"
        : "=l"(d) : "r"(v));
    return d;
}

// ---------------- constant tables ----------------
// H[]: ALL layer weights/biases as f16x2 duplicated (w,w), u32.
// D[]: f32x2 tail constants. Scalar compile-time indices only -> LDCU.
enum {
    O_W1 = 0,   O_B1 = 128,
    O_W2 = 144, O_B2 = 400,
    O_W3 = 416, O_B3 = 608,
    O_W4 = 620, O_B4 = 716,
    O_W5 = 724, O_B5 = 756,
    O_WH = 760, O_BH = 776,
    W_TOTAL = 780
};
enum { D_TOTAL = 21 };  // D[0..17]=Wf dup, D[18]=bf0, D[19]=bf1, D[20]=-gamma*log2e

struct CParams {
    u32 H[W_TOTAL];
    u64 D[D_TOTAL];
    u32 pad;
};

__constant__ CParams cP;
__device__ CParams gScratch;

#define LOG2E 1.4426950408889634f
#define LN2   0.6931471805599453f

// ---------------- parallel prep: one thread per table element ----------------
// Flat index space: [0, 780) -> H segments, [780, 801) -> D entries.
// All LDGs issue concurrently (one latency chain, not twelve serial loops).
__global__ void prep_kernel(
    const float* __restrict__ W1, const float* __restrict__ b1,
    const float* __restrict__ W2, const float* __restrict__ b2,
    const float* __restrict__ W3, const float* __restrict__ b3,
    const float* __restrict__ W4, const float* __restrict__ b4,
    const float* __restrict__ W5, const float* __restrict__ b5,
    const float* __restrict__ Wh, const float* __restrict__ bh,
    const float* __restrict__ Wf, const float* __restrict__ bf,
    const float* __restrict__ gamma)
{
    int i = blockIdx.x * blockDim.x + threadIdx.x;
    if (i < W_TOTAL) {
        const float* src;
        int off;
        if      (i < O_B1) { src = W1; off = i - O_W1; }
        else if (i < O_W2) { src = b1; off = i - O_B1; }
        else if (i < O_B2) { src = W2; off = i - O_W2; }
        else if (i < O_W3) { src = b2; off = i - O_B2; }
        else if (i < O_B3) { src = W3; off = i - O_W3; }
        else if (i < O_W4) { src = b3; off = i - O_B3; }
        else if (i < O_B4) { src = W4; off = i - O_W4; }
        else if (i < O_W5) { src = b4; off = i - O_B4; }
        else if (i < O_B5) { src = W5; off = i - O_W5; }
        else if (i < O_WH) { src = b5; off = i - O_B5; }
        else if (i < O_BH) { src = Wh; off = i - O_WH; }
        else               { src = bh; off = i - O_BH; }
        float f = src[off];
        u32 h;
        asm("cvt.rn.f16x2.f32 %0, %1, %1;" : "=r"(h) : "f"(f));
        gScratch.H[i] = h;
    } else if (i < W_TOTAL + D_TOTAL) {
        int j = i - W_TOTAL;
        float f;
        if (j < 18)       f = Wf[j];
        else if (j == 18) f = bf[0];
        else if (j == 19) f = bf[1];
        else              f = -gamma[0] * LOG2E;
        gScratch.D[j] = pack2(f, f);
    }
}

// ---------------- fp16x2 dense layer on TWO packed pairs (4 samples) ----------------
template <int OFF_W, int OFF_B, int IN, int OUT, bool ACT>
__device__ __forceinline__ void layer_h(const u32* __restrict__ in0, const u32* __restrict__ in1,
                                        u32* __restrict__ out0, u32* __restrict__ out1) {
#pragma unroll
    for (int j = 0; j < OUT; j++) {
        u32 a0 = cP.H[OFF_B + j];
        u32 a1 = a0;
#pragma unroll
        for (int i = 0; i < IN; i++) {
            u32 w = cP.H[OFF_W + j * IN + i];
            a0 = hfma2(in0[i], w, a0);
            a1 = hfma2(in1[i], w, a1);
        }
        if (ACT) { a0 = tanh_h2(a0); a1 = tanh_h2(a1); }
        out0[j] = a0;
        out1[j] = a1;
    }
}

// ---- f32 tail ----
__device__ __forceinline__ void tail_pair(const u64* __restrict__ A, u64& o0, u64& o1) {
    u64 s2 = mul2(A[0], A[0]);
    s2 = ffma2(A[1], A[1], s2);
    s2 = ffma2(A[2], A[2], s2);
    s2 = ffma2(A[3], A[3], s2);
    u64 g = mul2(s2, cP.D[20]);
    float glo, ghi;
    unpack2(g, glo, ghi);
    u64 k = pack2(ex2_ap(glo), ex2_ap(ghi));
    o0 = cP.D[18];
    o0 = ffma2(A[0], cP.D[0], o0);
    o0 = ffma2(A[1], cP.D[1], o0);
    o0 = ffma2(A[2], cP.D[2], o0);
    o0 = ffma2(A[3], cP.D[3], o0);
    o0 = ffma2(k,    cP.D[8], o0);
    o1 = cP.D[19];
    o1 = ffma2(A[0], cP.D[9],  o1);
    o1 = ffma2(A[1], cP.D[10], o1);
    o1 = ffma2(A[2], cP.D[11], o1);
    o1 = ffma2(A[3], cP.D[12], o1);
    o1 = ffma2(k,    cP.D[17], o1);
}

__device__ __forceinline__ void lsm2(float a, float b, float& ra, float& rb) {
    float m  = fmaxf(a, b);
    float mn = fminf(a, b);
    float lse = m + lg2_ap(1.0f + ex2_ap((mn - m) * LOG2E)) * LN2;
    ra = a - lse; rb = b - lse;
}

template <bool EXACT>
__global__ __launch_bounds__(128, 4) void qcnn_kernel(
    const float* __restrict__ x, float* __restrict__ out, int nb)
{
    int t = blockIdx.x * blockDim.x + threadIdx.x;
    int base = t * 4;
    if (!EXACT && base >= nb) return;

    // ---- load 4 samples, convert once to f16x2 (sample-pairs in lo/hi) ----
    u32 H0[16], H1[16], G0[16], G1[16];
    {
        const float4* p0 = (const float4*)(x + (size_t)base * 8);
        float4 a, b, c, d, e, f, g, h;
        if (EXACT) {
            a = p0[0]; b = p0[1]; c = p0[2]; d = p0[3];
            e = p0[4]; f = p0[5]; g = p0[6]; h = p0[7];
        } else {
            int s1 = (base + 1 < nb) ? base + 1 : nb - 1;
            int s2 = (base + 2 < nb) ? base + 2 : nb - 1;
            int s3 = (base + 3 < nb) ? base + 3 : nb - 1;
            const float4* p1 = (const float4*)(x + (size_t)s1 * 8);
            const float4* p2 = (const float4*)(x + (size_t)s2 * 8);
            const float4* p3 = (const float4*)(x + (size_t)s3 * 8);
            a = p0[0]; b = p0[1];
            c = p1[0]; d = p1[1];
            e = p2[0]; f = p2[1];
            g = p3[0]; h = p3[1];
        }
        H0[0] = pack_h2(a.x, c.x); H0[1] = pack_h2(a.y, c.y);
        H0[2] = pack_h2(a.z, c.z); H0[3] = pack_h2(a.w, c.w);
        H0[4] = pack_h2(b.x, d.x); H0[5] = pack_h2(b.y, d.y);
        H0[6] = pack_h2(b.z, d.z); H0[7] = pack_h2(b.w, d.w);
        H1[0] = pack_h2(e.x, g.x); H1[1] = pack_h2(e.y, g.y);
        H1[2] = pack_h2(e.z, g.z); H1[3] = pack_h2(e.w, g.w);
        H1[4] = pack_h2(f.x, h.x); H1[5] = pack_h2(f.y, h.y);
        H1[6] = pack_h2(f.z, h.z); H1[7] = pack_h2(f.w, h.w);
    }

    layer_h<O_W1, O_B1, 8,  16, true >(H0, H1, G0, G1);
    layer_h<O_W2, O_B2, 16, 16, true >(G0, G1, H0, H1);
    layer_h<O_W3, O_B3, 16, 12, true >(H0, H1, G0, G1);
    layer_h<O_W4, O_B4, 12, 8,  true >(G0, G1, H0, H1);
    layer_h<O_W5, O_B5, 8,  4,  true >(H0, H1, G0, G1);
    layer_h<O_WH, O_BH, 4,  4,  false>(G0, G1, H0, H1);   // cls_out (h2) in H0/H1[0..3]

    // ---- convert cls_out to f32x2 and run the f32 tail ----
    u64 A0[4], A1[4];
#pragma unroll
    for (int j = 0; j < 4; j++) {
        A0[j] = h2_to_f32x2(H0[j]);
        A1[j] = h2_to_f32x2(H1[j]);
    }

    u64 p00, p01, p10, p11;
    tail_pair(A0, p00, p01);   // samples 0,1
    tail_pair(A1, p10, p11);   // samples 2,3

    float l00a, l01a, l00b, l01b;
    unpack2(p00, l00a, l00b);
    unpack2(p01, l01a, l01b);
    float l10a, l11a, l10b, l11b;
    unpack2(p10, l10a, l10b);
    unpack2(p11, l11a, l11b);

    float r0a, r0b, r1a, r1b, r2a, r2b, r3a, r3b;
    lsm2(l00a, l01a, r0a, r0b);    // sample 0
    lsm2(l00b, l01b, r1a, r1b);    // sample 1
    lsm2(l10a, l11a, r2a, r2b);    // sample 2
    lsm2(l10b, l11b, r3a, r3b);    // sample 3

    if (EXACT || base + 4 <= nb) {
        float4* po = (float4*)(out + (size_t)base * 2);
        po[0] = make_float4(r0a, r0b, r1a, r1b);
        po[1] = make_float4(r2a, r2b, r3a, r3b);
    } else {
        float rs[4][2] = {{r0a, r0b}, {r1a, r1b}, {r2a, r2b}, {r3a, r3b}};
#pragma unroll
        for (int s = 0; s < 4; s++) {
            if (base + s < nb) {
                out[(base + s) * 2 + 0] = rs[s][0];
                out[(base + s) * 2 + 1] = rs[s][1];
            }
        }
    }
}

extern "C" void kernel_launch(void* const* d_in, const int* in_sizes, int n_in,
                              void* d_out, int out_size) {
    const float* x  = (const float*)d_in[0];
    const float* W1 = (const float*)d_in[1];
    const float* b1 = (const float*)d_in[2];
    const float* W2 = (const float*)d_in[3];
    const float* b2 = (const float*)d_in[4];
    const float* W3 = (const float*)d_in[5];
    const float* b3 = (const float*)d_in[6];
    const float* W4 = (const float*)d_in[7];
    const float* b4 = (const float*)d_in[8];
    const float* W5 = (const float*)d_in[9];
    const float* b5 = (const float*)d_in[10];
    const float* Wh = (const float*)d_in[11];
    const float* bh = (const float*)d_in[12];
    const float* Wf = (const float*)d_in[13];
    const float* bf = (const float*)d_in[14];
    const float* gm = (const float*)d_in[15];

    // 1) parallel prep: one thread per table element (all LDGs concurrent)
    {
        int total = W_TOTAL + D_TOTAL;
        int threads = 128;
        int blocks = (total + threads - 1) / threads;
        prep_kernel<<<blocks, threads>>>(W1, b1, W2, b2, W3, b3, W4, b4, W5, b5,
                                         Wh, bh, Wf, bf, gm);
    }

    // 2) move into the constant bank (D2D async copy — graph-capturable)
    void* scratch_addr = nullptr;
    cudaGetSymbolAddress(&scratch_addr, gScratch);
    cudaMemcpyToSymbolAsync(cP, scratch_addr, sizeof(CParams), 0,
                            cudaMemcpyDeviceToDevice, 0);

    // 3) main kernel — exact-grid specialization when nb divides evenly
    int nb = in_sizes[0] / 8;
    int threads = 128;
    int spb = threads * 4;
    if (nb % spb == 0) {
        qcnn_kernel<true><<<nb / spb, threads>>>(x, (float*)d_out, nb);
    } else {
        qcnn_kernel<false><<<(nb + spb - 1) / spb, threads>>>(x, (float*)d_out, nb);
    }
}